// round 15
// baseline (speedup 1.0000x reference)
#include <cuda_runtime.h>
#include <cuda_fp16.h>

// ============================================================================
// FrFDConv via fp16 tensor-core implicit GEMM (mma.sync m16n8k16.f16, f32 acc).
// R15: occupancy push. Warp tile 2m x 8n (64 acc regs, ~110 regs/thread) ->
// 4 blocks/SM (16 warps, 4/SMSP) with independent per-block barriers, so
// staging/sync windows of one block hide behind mma issue of three others.
//   GEMM: M = 16*224*224, N = 64 co, K = 576 = 4 chunks * 16 ci * 9 taps.
//   Block M = 128 (4 h x 32 w); patch plane stride 232 words (== 8 mod 32)
//   keeps all A-fragment LDS bank-conflict-free.
// ============================================================================

#define PI_F 3.14159265358979323846f
typedef unsigned int u32;

// K[co][k], k = ci*9 + tap (fp32)
__device__ float g_wK[64 * 576];
// B fragments: [s(36)][nt(8)][lane(32)] -> uint2 {b0(half2), b1(half2)}
__device__ uint2 g_BfragH[36 * 8 * 32];

// ------------------------------ complex helpers -----------------------------
struct c2f { float re, im; };
__device__ __forceinline__ c2f cmul(c2f a, c2f b) {
    return { a.re * b.re - a.im * b.im, a.re * b.im + a.im * b.re };
}
__device__ __forceinline__ c2f cadd(c2f a, c2f b) { return { a.re + b.re, a.im + b.im }; }
__device__ __forceinline__ c2f cscale(c2f a, float s) { return { a.re * s, a.im * s }; }
__device__ __forceinline__ c2f cis(float th) {
    float s, c; sincosf(th, &s, &c); return { c, s };
}

__device__ __forceinline__ void frft3(c2f& v0, c2f& v1, c2f& v2,
                                      c2f c1a, c2f c1b, c2f c2a, c2f c2b,
                                      float scl) {
    const c2f w  = { -0.5f, -0.8660254037844386f };
    const c2f wb = { -0.5f,  0.8660254037844386f };
    c2f u0 = cmul(v1, c1a);
    c2f u1 = cmul(v2, c1b);
    c2f u2 = v0;
    c2f F0 = cadd(cadd(u0, u1), u2);
    c2f F1 = cadd(cadd(u0, cmul(u1, w )), cmul(u2, wb));
    c2f F2 = cadd(cadd(u0, cmul(u1, wb)), cmul(u2, w ));
    c2f G0 = cmul(F0, c2a);
    c2f G1 = cmul(F1, c2b);
    c2f G2 = F2;
    c2f y0 = cadd(cadd(G0, G1), G2);
    c2f y1 = cadd(cadd(G0, cmul(G1, wb)), cmul(G2, w ));
    c2f y2 = cadd(cadd(G0, cmul(G1, w )), cmul(G2, wb));
    float t3 = scl * (1.0f / 3.0f);
    c2f z0 = cscale(cmul(y0, c1a), t3);
    c2f z1 = cscale(cmul(y1, c1b), t3);
    c2f z2 = cscale(y2, t3);
    v0 = z2; v1 = z0; v2 = z1;
}

// ----------------------------- weight generation ----------------------------
__global__ void frfd_wgen_kernel(const float* __restrict__ spec,
                                 const float* __restrict__ alphap,
                                 const float* __restrict__ polarw) {
    int id = blockIdx.x * blockDim.x + threadIdx.x;
    if (id >= 64 * 64) return;

    float a = alphap[0];
    a = fminf(fmaxf(a, 1e-4f), 2.0f - 1e-4f);
    float t  = tanf(a * PI_F * 0.25f);
    float sa = sinf(a * PI_F * 0.5f);
    float scl = rsqrtf(fabsf(sa) + 1e-12f);
    c2f c1a = cis(-PI_F * 4.0f * t * (1.0f / 3.0f));
    c2f c1b = cis(-PI_F * t * (1.0f / 3.0f));
    float inv3sa = 1.0f / (3.0f * sa);
    c2f c2a = cis(-PI_F * 4.0f * inv3sa);
    c2f c2b = cis(-PI_F * inv3sa);

    c2f Z[3][3];
    const float* sp = spec + (size_t)id * 9;
#pragma unroll
    for (int i = 0; i < 3; i++)
#pragma unroll
        for (int j = 0; j < 3; j++)
            Z[i][j] = { sp[i * 3 + j], 0.0f };
#pragma unroll
    for (int i = 0; i < 3; i++)
        frft3(Z[i][0], Z[i][1], Z[i][2], c1a, c1b, c2a, c2b, scl);
#pragma unroll
    for (int j = 0; j < 3; j++)
        frft3(Z[0][j], Z[1][j], Z[2][j], c1a, c1b, c2a, c2b, scl);

    float pw0 = polarw[0];
    float pw1 = polarw[1];
    int co = id >> 6, ci = id & 63;
    float* gw = g_wK + co * 576 + ci * 9;
#pragma unroll
    for (int i = 0; i < 3; i++)
#pragma unroll
        for (int j = 0; j < 3; j++) {
            float re = Z[i][j].re, im = Z[i][j].im;
            float mag = sqrtf(re * re + im * im);
            float ang = atan2f(im, re);
            gw[i * 3 + j] = pw0 * mag + pw1 * (ang * (1.0f / PI_F));
        }
}

// ---------------- B-fragment build: g_wK -> g_BfragH (fp16) ----------------
// Step s = ch*9 + tap, chunk ch covers ci = ch*16 .. ch*16+15.
// b0 = {W[co][c0+2tig][tap], W[co][c0+2tig+1][tap]}, b1 = same with ci += 8.
__global__ void frfd_bfragH_kernel() {
    int s   = blockIdx.x;           // 0..35
    int tid = threadIdx.x;          // 256 = 8 nt * 32 lanes
    int nt   = tid >> 5;
    int lane = tid & 31;
    int gid  = lane >> 2;
    int tig  = lane & 3;
    int ch  = s / 9;
    int tap = s - ch * 9;
    int co  = nt * 8 + gid;
    int c0  = ch * 16;

    float w00 = g_wK[co * 576 + (c0 + 2 * tig)     * 9 + tap];
    float w01 = g_wK[co * 576 + (c0 + 2 * tig + 1) * 9 + tap];
    float w10 = g_wK[co * 576 + (c0 + 8 + 2 * tig)     * 9 + tap];
    float w11 = g_wK[co * 576 + (c0 + 8 + 2 * tig + 1) * 9 + tap];

    __half2 h0 = __floats2half2_rn(w00, w01);
    __half2 h1 = __floats2half2_rn(w10, w11);
    uint2 packed;
    packed.x = *reinterpret_cast<u32*>(&h0);
    packed.y = *reinterpret_cast<u32*>(&h1);
    g_BfragH[(s * 8 + nt) * 32 + lane] = packed;
}

// --------------------------------- conv mma ---------------------------------
__device__ __forceinline__ void mma16(float* c,
                                      u32 a0, u32 a1, u32 a2, u32 a3,
                                      u32 b0, u32 b1) {
    asm volatile(
        "mma.sync.aligned.m16n8k16.row.col.f32.f16.f16.f32 "
        "{%0,%1,%2,%3}, {%4,%5,%6,%7}, {%8,%9}, {%0,%1,%2,%3};"
        : "+f"(c[0]), "+f"(c[1]), "+f"(c[2]), "+f"(c[3])
        : "r"(a0), "r"(a1), "r"(a2), "r"(a3), "r"(b0), "r"(b1));
}

// Patch plane: 6 rows x 36 cols (34 used) padded to 232 words (== 8 mod 32).
#define PLANE 232
#define PWORDS 1632   // 8 planes * 6 * 34 useful words per chunk

__global__ __launch_bounds__(128, 4)
void frfd_conv_mma(const float* __restrict__ x, float* __restrict__ out) {
    // double-buffered A: [buf][ci2(8) planes of PLANE words] half2 words
    __shared__ __align__(16) u32 sA[2][8 * PLANE];

    const int tid  = threadIdx.x;       // 128
    const int wz   = tid >> 5;          // warp 0..3 -> h row
    const int lane = tid & 31;
    const int gid  = lane >> 2;
    const int tig  = lane & 3;

    const int w0 = blockIdx.x * 32;
    const int h0 = blockIdx.y * 4;
    const int n  = blockIdx.z;

    // per-thread A word offsets for the 9 tap-steps:
    //   lo: ci2 = tig, hi: ci2 = tig + 4; tig stride PLANE == 8 mod 32.
    u32 dApack[9];
#pragma unroll
    for (int kt = 0; kt < 9; ++kt) {
        int tapoff = (kt / 3) * 36 + (kt % 3);
        int lo = tig * PLANE + tapoff;
        int hi = lo + 4 * PLANE;
        dApack[kt] = (u32)lo | ((u32)hi << 16);
    }

    // 2 m-tiles: col halves of this warp's row
    int mBase[2];
#pragma unroll
    for (int wt = 0; wt < 2; ++wt)
        mBase[wt] = wz * 36 + wt * 16 + gid;

    float acc[2][8][4];
#pragma unroll
    for (int wt = 0; wt < 2; ++wt)
#pragma unroll
        for (int nt = 0; nt < 8; ++nt)
#pragma unroll
            for (int c = 0; c < 4; ++c) acc[wt][nt][c] = 0.0f;

    const float* xb = x + (size_t)n * 64 * 50176;

    // ---- prologue: stage chunk 0 (ci 0..15 as 8 half2 planes) ----
    for (int idx = tid; idx < PWORDS; idx += 128) {
        int ci2 = idx / 204;
        int rem = idx - ci2 * 204;
        int r   = rem / 34;
        int c   = rem - r * 34;
        int gh = h0 - 1 + r;
        int gw = w0 - 1 + c;
        float v0 = 0.0f, v1 = 0.0f;
        if ((unsigned)gh < 224u && (unsigned)gw < 224u) {
            const float* p = xb + (size_t)(2 * ci2) * 50176 + gh * 224 + gw;
            v0 = __ldg(p);
            v1 = __ldg(p + 50176);
        }
        __half2 h = __floats2half2_rn(v0, v1);
        sA[0][ci2 * PLANE + r * 36 + c] = *reinterpret_cast<u32*>(&h);
    }
    __syncthreads();

    for (int ch = 0; ch < 4; ++ch) {
        const u32* __restrict__ aBuf = sA[ch & 1];

        // ---- prefetch chunk ch+1 into registers (fly during mma) ----
        u32 vpre[13];
        if (ch < 3) {
            const float* xc = xb + (size_t)(ch + 1) * 16 * 50176;
#pragma unroll
            for (int k = 0; k < 13; ++k) {
                int idx = tid + k * 128;
                float v0 = 0.0f, v1 = 0.0f;
                if (idx < PWORDS) {
                    int ci2 = idx / 204;
                    int rem = idx - ci2 * 204;
                    int r   = rem / 34;
                    int c   = rem - r * 34;
                    int gh = h0 - 1 + r;
                    int gw = w0 - 1 + c;
                    if ((unsigned)gh < 224u && (unsigned)gw < 224u) {
                        const float* p = xc + (size_t)(2 * ci2) * 50176 + gh * 224 + gw;
                        v0 = __ldg(p);
                        v1 = __ldg(p + 50176);
                    }
                }
                __half2 h = __floats2half2_rn(v0, v1);
                vpre[k] = *reinterpret_cast<u32*>(&h);
            }
        }

        // ---- 9 tap-steps x (2 m-tiles x 8 n-tiles) k16 mma ----
        const uint2* bChunk = g_BfragH + (size_t)ch * 9 * 8 * 32 + lane;
#pragma unroll 3
        for (int kt = 0; kt < 9; ++kt) {
            u32 p = dApack[kt];
            const u32* aLo = aBuf + (p & 0xFFFFu);
            const u32* aHi = aBuf + (p >> 16);
            u32 a[2][4];
#pragma unroll
            for (int wt = 0; wt < 2; ++wt) {
                int b = mBase[wt];
                a[wt][0] = aLo[b];        // rows g,   k 2t..2t+1
                a[wt][1] = aLo[b + 8];    // rows g+8, k 2t..2t+1
                a[wt][2] = aHi[b];        // rows g,   k 2t+8..2t+9
                a[wt][3] = aHi[b + 8];    // rows g+8, k 2t+8..2t+9
            }
            const uint2* bp = bChunk + (size_t)kt * 256;
#pragma unroll
            for (int nt = 0; nt < 8; ++nt) {
                uint2 bb = __ldg(bp + nt * 32);
#pragma unroll
                for (int wt = 0; wt < 2; ++wt)
                    mma16(acc[wt][nt],
                          a[wt][0], a[wt][1], a[wt][2], a[wt][3],
                          bb.x, bb.y);
            }
        }

        // ---- store prefetched chunk into the other buffer ----
        if (ch < 3) {
            u32* dst = sA[(ch + 1) & 1];
#pragma unroll
            for (int k = 0; k < 13; ++k) {
                int idx = tid + k * 128;
                if (idx < PWORDS) {
                    int ci2 = idx / 204;
                    int rem = idx - ci2 * 204;
                    int r   = rem / 34;
                    int c   = rem - r * 34;
                    dst[ci2 * PLANE + r * 36 + c] = vpre[k];
                }
            }
        }
        __syncthreads();
    }

    // ---- epilogue: scatter stores (m16n8 C layout) ----
    float* ob = out + (size_t)n * 64 * 50176;
    const int h = h0 + wz;
#pragma unroll
    for (int nt = 0; nt < 8; ++nt) {
        int co = nt * 8 + tig * 2;
        float* p0 = ob + (size_t)co * 50176 + (size_t)h * 224 + w0 + gid;
        float* p1 = p0 + 50176;
#pragma unroll
        for (int wt = 0; wt < 2; ++wt) {
            float* q0 = p0 + wt * 16;
            float* q1 = p1 + wt * 16;
            q0[0] = acc[wt][nt][0];
            q1[0] = acc[wt][nt][1];
            q0[8] = acc[wt][nt][2];
            q1[8] = acc[wt][nt][3];
        }
    }
}

// --------------------------------- launcher ---------------------------------
extern "C" void kernel_launch(void* const* d_in, const int* in_sizes, int n_in,
                              void* d_out, int out_size) {
    int ix = 0, ispec = 1, ialpha = 2, ipw = 3;
    for (int i = 0; i < n_in; ++i) {
        int s = in_sizes[i];
        if (s == 16 * 64 * 224 * 224) ix = i;
        else if (s == 64 * 64 * 3 * 3) ispec = i;
        else if (s == 1) ialpha = i;
        else if (s == 2) ipw = i;
    }
    const float* x     = (const float*)d_in[ix];
    const float* spec  = (const float*)d_in[ispec];
    const float* alpha = (const float*)d_in[ialpha];
    const float* pw    = (const float*)d_in[ipw];
    float* out = (float*)d_out;

    frfd_wgen_kernel<<<16, 256>>>(spec, alpha, pw);
    frfd_bfragH_kernel<<<36, 256>>>();

    dim3 grid(7, 56, 16);
    frfd_conv_mma<<<grid, 128>>>(x, out);
}

// round 16
// speedup vs baseline: 1.2235x; 1.2235x over previous
#include <cuda_runtime.h>
#include <cuda_fp16.h>

// ============================================================================
// FrFDConv via fp16 tensor-core implicit GEMM (mma.sync m16n8k16.f16, f32 acc).
// R16: persistent blocks + seamless cross-tile prefetch pipeline.
//   - 296 persistent blocks (2/SM), each loops ~10-11 tiles: no wave tail.
//   - last chunk of tile t prefetches chunk 0 of tile t+1 (buffer parity is
//     continuous), so staging is never exposed after the one-time prologue.
//   - weight gen fused into ONE kernel: FrFT -> B fragments via __shfl pairing.
//   GEMM: M = 16*224*224, N = 64 co, K = 576 = 4 chunks * 16 ci * 9 taps.
//   Warp tile 4m x 8n (proven R13 shape), A-LDS bank-conflict-free.
// ============================================================================

#define PI_F 3.14159265358979323846f
typedef unsigned int u32;

#define NTILES 3136            // 7 wx * 28 hy * 16 n
#define NBLOCKS 296            // 148 SMs * 2

// B fragments, u32 view: [s(36)][nt(8)][lane(32)][2] ; pair = {b0,b1} half2
__device__ u32 g_BfragW[36 * 8 * 32 * 2];

// ------------------------------ complex helpers -----------------------------
struct c2f { float re, im; };
__device__ __forceinline__ c2f cmul(c2f a, c2f b) {
    return { a.re * b.re - a.im * b.im, a.re * b.im + a.im * b.re };
}
__device__ __forceinline__ c2f cadd(c2f a, c2f b) { return { a.re + b.re, a.im + b.im }; }
__device__ __forceinline__ c2f cscale(c2f a, float s) { return { a.re * s, a.im * s }; }
__device__ __forceinline__ c2f cis(float th) {
    float s, c; sincosf(th, &s, &c); return { c, s };
}

__device__ __forceinline__ void frft3(c2f& v0, c2f& v1, c2f& v2,
                                      c2f c1a, c2f c1b, c2f c2a, c2f c2b,
                                      float scl) {
    const c2f w  = { -0.5f, -0.8660254037844386f };
    const c2f wb = { -0.5f,  0.8660254037844386f };
    c2f u0 = cmul(v1, c1a);
    c2f u1 = cmul(v2, c1b);
    c2f u2 = v0;
    c2f F0 = cadd(cadd(u0, u1), u2);
    c2f F1 = cadd(cadd(u0, cmul(u1, w )), cmul(u2, wb));
    c2f F2 = cadd(cadd(u0, cmul(u1, wb)), cmul(u2, w ));
    c2f G0 = cmul(F0, c2a);
    c2f G1 = cmul(F1, c2b);
    c2f G2 = F2;
    c2f y0 = cadd(cadd(G0, G1), G2);
    c2f y1 = cadd(cadd(G0, cmul(G1, wb)), cmul(G2, w ));
    c2f y2 = cadd(cadd(G0, cmul(G1, w )), cmul(G2, wb));
    float t3 = scl * (1.0f / 3.0f);
    c2f z0 = cscale(cmul(y0, c1a), t3);
    c2f z1 = cscale(cmul(y1, c1b), t3);
    c2f z2 = cscale(y2, t3);
    v0 = z2; v1 = z0; v2 = z1;
}

// ------------- fused weight generation: FrFT -> B fragments -----------------
// Thread id = co*64 + ci. Warp spans 32 consecutive ci of one co, so the
// (ci, ci+1) half2 pairing is a __shfl_down of 1 lane.
// Fragment layout (matches conv): s = ch*9+tap, ch = ci>>4, r = ci&15;
//   r<8  -> b0 (word 0), tig = r>>1 ;  r>=8 -> b1 (word 1), tig = (r-8)>>1
//   u32 index = ((s*8 + nt)*32 + gid*4 + tig)*2 + (r<8 ? 0 : 1)
__global__ void frfd_wgen_kernel(const float* __restrict__ spec,
                                 const float* __restrict__ alphap,
                                 const float* __restrict__ polarw) {
    int id = blockIdx.x * blockDim.x + threadIdx.x;
    if (id >= 64 * 64) return;

    float a = alphap[0];
    a = fminf(fmaxf(a, 1e-4f), 2.0f - 1e-4f);
    float t  = tanf(a * PI_F * 0.25f);
    float sa = sinf(a * PI_F * 0.5f);
    float scl = rsqrtf(fabsf(sa) + 1e-12f);
    c2f c1a = cis(-PI_F * 4.0f * t * (1.0f / 3.0f));
    c2f c1b = cis(-PI_F * t * (1.0f / 3.0f));
    float inv3sa = 1.0f / (3.0f * sa);
    c2f c2a = cis(-PI_F * 4.0f * inv3sa);
    c2f c2b = cis(-PI_F * inv3sa);

    c2f Z[3][3];
    const float* sp = spec + (size_t)id * 9;
#pragma unroll
    for (int i = 0; i < 3; i++)
#pragma unroll
        for (int j = 0; j < 3; j++)
            Z[i][j] = { sp[i * 3 + j], 0.0f };
#pragma unroll
    for (int i = 0; i < 3; i++)
        frft3(Z[i][0], Z[i][1], Z[i][2], c1a, c1b, c2a, c2b, scl);
#pragma unroll
    for (int j = 0; j < 3; j++)
        frft3(Z[0][j], Z[1][j], Z[2][j], c1a, c1b, c2a, c2b, scl);

    float pw0 = polarw[0];
    float pw1 = polarw[1];

    int co = id >> 6, ci = id & 63;
    int nt = co >> 3, gid = co & 7;
    int ch = ci >> 4, r = ci & 15;
    int tig  = (r < 8) ? (r >> 1) : ((r - 8) >> 1);
    int word = (r < 8) ? 0 : 1;
    bool writer = ((ci & 1) == 0);

#pragma unroll
    for (int i = 0; i < 3; i++)
#pragma unroll
        for (int j = 0; j < 3; j++) {
            float re = Z[i][j].re, im = Z[i][j].im;
            float mag = sqrtf(re * re + im * im);
            float ang = atan2f(im, re);
            float k = pw0 * mag + pw1 * (ang * (1.0f / PI_F));
            float kn = __shfl_down_sync(0xffffffffu, k, 1);
            if (writer) {
                int tap = i * 3 + j;
                int s = ch * 9 + tap;
                __half2 h = __floats2half2_rn(k, kn);
                g_BfragW[(((s * 8 + nt) * 32) + gid * 4 + tig) * 2 + word] =
                    *reinterpret_cast<u32*>(&h);
            }
        }
}

// --------------------------------- conv mma ---------------------------------
__device__ __forceinline__ void mma16(float* c,
                                      u32 a0, u32 a1, u32 a2, u32 a3,
                                      u32 b0, u32 b1) {
    asm volatile(
        "mma.sync.aligned.m16n8k16.row.col.f32.f16.f16.f32 "
        "{%0,%1,%2,%3}, {%4,%5,%6,%7}, {%8,%9}, {%0,%1,%2,%3};"
        : "+f"(c[0]), "+f"(c[1]), "+f"(c[2]), "+f"(c[3])
        : "r"(a0), "r"(a1), "r"(a2), "r"(a3), "r"(b0), "r"(b1));
}

// tile decode: tile = n*196 + hy*7 + wx
__device__ __forceinline__ void tile_coords(int tile, int& h0, int& w0, int& n) {
    int wx = tile % 7;
    int r1 = tile / 7;
    int hy = r1 % 28;
    n = r1 / 28;
    w0 = wx * 32;
    h0 = hy * 8;
}

__global__ __launch_bounds__(128, 2)
void frfd_conv_mma(const float* __restrict__ x, float* __restrict__ out) {
    // double-buffered A: [buf][ci2(8)][row(10)][col(36, 34 used)] half2 words
    __shared__ __align__(16) u32 sA[2][8 * 10 * 36];

    const int tid  = threadIdx.x;       // 128
    const int wz   = tid >> 5;          // warp 0..3 -> h row pair
    const int lane = tid & 31;
    const int gid  = lane >> 2;
    const int tig  = lane & 3;

    // per-thread A word offsets for the 9 tap-steps (conflict-free LDS)
    u32 dApack[9];
#pragma unroll
    for (int kt = 0; kt < 9; ++kt) {
        int tapoff = (kt / 3) * 36 + (kt % 3);
        int lo = tig * 360 + tapoff;
        int hi = lo + 4 * 360;
        dApack[kt] = (u32)lo | ((u32)hi << 16);
    }

    int mBase[2][2];
#pragma unroll
    for (int rh = 0; rh < 2; ++rh)
#pragma unroll
        for (int wt = 0; wt < 2; ++wt)
            mBase[rh][wt] = (2 * wz + rh) * 36 + wt * 16 + gid;

    const uint2* bTab = reinterpret_cast<const uint2*>(g_BfragW);

    // ---- one-time prologue: stage (tile0, chunk0) into buffer 0 ----
    {
        int h0, w0, n;
        tile_coords(blockIdx.x, h0, w0, n);
        const float* xb = x + (size_t)n * 64 * 50176;
        for (int idx = tid; idx < 2720; idx += 128) {
            int ci2 = idx / 340;
            int rem = idx - ci2 * 340;
            int r   = rem / 34;
            int c   = rem - r * 34;
            int gh = h0 - 1 + r;
            int gw = w0 - 1 + c;
            float v0 = 0.0f, v1 = 0.0f;
            if ((unsigned)gh < 224u && (unsigned)gw < 224u) {
                const float* p = xb + (size_t)(2 * ci2) * 50176 + gh * 224 + gw;
                v0 = __ldg(p);
                v1 = __ldg(p + 50176);
            }
            __half2 h = __floats2half2_rn(v0, v1);
            sA[0][ci2 * 360 + r * 36 + c] = *reinterpret_cast<u32*>(&h);
        }
    }
    __syncthreads();

    int p = 0;   // buffer parity (4 flips per tile -> consistent across tiles)

    for (int tile = blockIdx.x; tile < NTILES; tile += NBLOCKS) {
        int h0, w0, n;
        tile_coords(tile, h0, w0, n);

        float acc[2][2][8][4];
#pragma unroll
        for (int rh = 0; rh < 2; ++rh)
#pragma unroll
            for (int wt = 0; wt < 2; ++wt)
#pragma unroll
                for (int nt = 0; nt < 8; ++nt)
#pragma unroll
                    for (int c = 0; c < 4; ++c) acc[rh][wt][nt][c] = 0.0f;

        for (int ch = 0; ch < 4; ++ch) {
            const u32* __restrict__ aBuf = sA[p];

            // ---- prefetch target: (tile, ch+1) or (tile+NBLOCKS, chunk 0) ----
            bool hasPre;
            int ph0, pw0l;
            const float* pxc;
            if (ch < 3) {
                hasPre = true;
                ph0 = h0; pw0l = w0;
                pxc = x + (size_t)n * 64 * 50176 + (size_t)(ch + 1) * 16 * 50176;
            } else {
                int ntile = tile + NBLOCKS;
                hasPre = (ntile < NTILES);
                int nn = 0;
                if (hasPre) tile_coords(ntile, ph0, pw0l, nn);
                else { ph0 = 0; pw0l = 0; }
                pxc = x + (size_t)nn * 64 * 50176;
            }

            u32 vpre[22];
            if (hasPre) {
#pragma unroll
                for (int k = 0; k < 22; ++k) {
                    int idx = tid + k * 128;
                    float v0 = 0.0f, v1 = 0.0f;
                    if (idx < 2720) {
                        int ci2 = idx / 340;
                        int rem = idx - ci2 * 340;
                        int r   = rem / 34;
                        int c   = rem - r * 34;
                        int gh = ph0 - 1 + r;
                        int gw = pw0l - 1 + c;
                        if ((unsigned)gh < 224u && (unsigned)gw < 224u) {
                            const float* pp = pxc + (size_t)(2 * ci2) * 50176 + gh * 224 + gw;
                            v0 = __ldg(pp);
                            v1 = __ldg(pp + 50176);
                        }
                    }
                    __half2 h = __floats2half2_rn(v0, v1);
                    vpre[k] = *reinterpret_cast<u32*>(&h);
                }
            }

            // ---- 9 tap-steps x (4 m-tiles x 8 n-tiles) k16 mma ----
            const uint2* bChunk = bTab + (size_t)ch * 9 * 8 * 32 + lane;
#pragma unroll 3
            for (int kt = 0; kt < 9; ++kt) {
                u32 pk = dApack[kt];
                const u32* aLo = aBuf + (pk & 0xFFFFu);
                const u32* aHi = aBuf + (pk >> 16);
                u32 a[2][2][4];
#pragma unroll
                for (int rh = 0; rh < 2; ++rh)
#pragma unroll
                    for (int wt = 0; wt < 2; ++wt) {
                        int b = mBase[rh][wt];
                        a[rh][wt][0] = aLo[b];
                        a[rh][wt][1] = aLo[b + 8];
                        a[rh][wt][2] = aHi[b];
                        a[rh][wt][3] = aHi[b + 8];
                    }
                const uint2* bp = bChunk + (size_t)kt * 256;
#pragma unroll
                for (int nt = 0; nt < 8; ++nt) {
                    uint2 bb = __ldg(bp + nt * 32);
#pragma unroll
                    for (int rh = 0; rh < 2; ++rh)
#pragma unroll
                        for (int wt = 0; wt < 2; ++wt)
                            mma16(acc[rh][wt][nt],
                                  a[rh][wt][0], a[rh][wt][1],
                                  a[rh][wt][2], a[rh][wt][3],
                                  bb.x, bb.y);
                }
            }

            // ---- store prefetched chunk into the other buffer ----
            if (hasPre) {
                u32* dst = sA[p ^ 1];
#pragma unroll
                for (int k = 0; k < 22; ++k) {
                    int idx = tid + k * 128;
                    if (idx < 2720) {
                        int ci2 = idx / 340;
                        int rem = idx - ci2 * 340;
                        int r   = rem / 34;
                        int c   = rem - r * 34;
                        dst[ci2 * 360 + r * 36 + c] = vpre[k];
                    }
                }
            }
            __syncthreads();
            p ^= 1;
        }

        // ---- epilogue: scatter stores for this tile ----
        float* ob = out + (size_t)n * 64 * 50176;
#pragma unroll
        for (int nt = 0; nt < 8; ++nt) {
            int co = nt * 8 + tig * 2;
#pragma unroll
            for (int rh = 0; rh < 2; ++rh) {
                int h = h0 + 2 * wz + rh;
                float* p0 = ob + (size_t)co * 50176 + (size_t)h * 224 + w0 + gid;
                float* p1 = p0 + 50176;
#pragma unroll
                for (int wt = 0; wt < 2; ++wt) {
                    float* q0 = p0 + wt * 16;
                    float* q1 = p1 + wt * 16;
                    q0[0] = acc[rh][wt][nt][0];
                    q1[0] = acc[rh][wt][nt][1];
                    q0[8] = acc[rh][wt][nt][2];
                    q1[8] = acc[rh][wt][nt][3];
                }
            }
        }
    }
}

// --------------------------------- launcher ---------------------------------
extern "C" void kernel_launch(void* const* d_in, const int* in_sizes, int n_in,
                              void* d_out, int out_size) {
    int ix = 0, ispec = 1, ialpha = 2, ipw = 3;
    for (int i = 0; i < n_in; ++i) {
        int s = in_sizes[i];
        if (s == 16 * 64 * 224 * 224) ix = i;
        else if (s == 64 * 64 * 3 * 3) ispec = i;
        else if (s == 1) ialpha = i;
        else if (s == 2) ipw = i;
    }
    const float* x     = (const float*)d_in[ix];
    const float* spec  = (const float*)d_in[ispec];
    const float* alpha = (const float*)d_in[ialpha];
    const float* pw    = (const float*)d_in[ipw];
    float* out = (float*)d_out;

    frfd_wgen_kernel<<<16, 256>>>(spec, alpha, pw);

    frfd_conv_mma<<<NBLOCKS, 128>>>(x, out);
}

// round 17
// speedup vs baseline: 1.2465x; 1.0188x over previous
#include <cuda_runtime.h>
#include <cuda_fp16.h>

// ============================================================================
// FrFDConv via fp16 tensor-core implicit GEMM (mma.sync m16n8k16.f16, f32 acc).
// R17: B-fragment table moved to SHARED MEMORY, staged once per persistent
// block. ncu R16 showed tensor=41.5% / issue=19%: warps stalled on B __ldg,
// whose L1 lines are continuously evicted by the x-patch stream. smem B is
// eviction-proof: every hot-loop B read becomes a 29-cyc conflict-free LDS.64.
//   - 296 persistent blocks (2/SM), seamless cross-tile prefetch (R16).
//   - dyn smem 96.8KB: [B 73728B][A ring 2 x 11520B].
//   GEMM: M = 16*224*224, N = 64 co, K = 576 = 4 chunks * 16 ci * 9 taps.
// ============================================================================

#define PI_F 3.14159265358979323846f
typedef unsigned int u32;

#define NTILES 3136            // 7 wx * 28 hy * 16 n
#define NBLOCKS 296            // 148 SMs * 2

#define B_WORDS (36 * 8 * 32 * 2)      // 18432 u32 = 73728 B
#define A_WORDS (8 * 10 * 36)          // 2880 u32 per buffer

// B fragments, u32 view: [s(36)][nt(8)][lane(32)][2] ; pair = {b0,b1} half2
__device__ u32 g_BfragW[B_WORDS];

// ------------------------------ complex helpers -----------------------------
struct c2f { float re, im; };
__device__ __forceinline__ c2f cmul(c2f a, c2f b) {
    return { a.re * b.re - a.im * b.im, a.re * b.im + a.im * b.re };
}
__device__ __forceinline__ c2f cadd(c2f a, c2f b) { return { a.re + b.re, a.im + b.im }; }
__device__ __forceinline__ c2f cscale(c2f a, float s) { return { a.re * s, a.im * s }; }
__device__ __forceinline__ c2f cis(float th) {
    float s, c; sincosf(th, &s, &c); return { c, s };
}

__device__ __forceinline__ void frft3(c2f& v0, c2f& v1, c2f& v2,
                                      c2f c1a, c2f c1b, c2f c2a, c2f c2b,
                                      float scl) {
    const c2f w  = { -0.5f, -0.8660254037844386f };
    const c2f wb = { -0.5f,  0.8660254037844386f };
    c2f u0 = cmul(v1, c1a);
    c2f u1 = cmul(v2, c1b);
    c2f u2 = v0;
    c2f F0 = cadd(cadd(u0, u1), u2);
    c2f F1 = cadd(cadd(u0, cmul(u1, w )), cmul(u2, wb));
    c2f F2 = cadd(cadd(u0, cmul(u1, wb)), cmul(u2, w ));
    c2f G0 = cmul(F0, c2a);
    c2f G1 = cmul(F1, c2b);
    c2f G2 = F2;
    c2f y0 = cadd(cadd(G0, G1), G2);
    c2f y1 = cadd(cadd(G0, cmul(G1, wb)), cmul(G2, w ));
    c2f y2 = cadd(cadd(G0, cmul(G1, w )), cmul(G2, wb));
    float t3 = scl * (1.0f / 3.0f);
    c2f z0 = cscale(cmul(y0, c1a), t3);
    c2f z1 = cscale(cmul(y1, c1b), t3);
    c2f z2 = cscale(y2, t3);
    v0 = z2; v1 = z0; v2 = z1;
}

// ------------- fused weight generation: FrFT -> B fragments -----------------
// Thread id = co*64 + ci; (ci, ci+1) half2 pairing via __shfl_down.
__global__ void frfd_wgen_kernel(const float* __restrict__ spec,
                                 const float* __restrict__ alphap,
                                 const float* __restrict__ polarw) {
    int id = blockIdx.x * blockDim.x + threadIdx.x;
    if (id >= 64 * 64) return;

    float a = alphap[0];
    a = fminf(fmaxf(a, 1e-4f), 2.0f - 1e-4f);
    float t  = tanf(a * PI_F * 0.25f);
    float sa = sinf(a * PI_F * 0.5f);
    float scl = rsqrtf(fabsf(sa) + 1e-12f);
    c2f c1a = cis(-PI_F * 4.0f * t * (1.0f / 3.0f));
    c2f c1b = cis(-PI_F * t * (1.0f / 3.0f));
    float inv3sa = 1.0f / (3.0f * sa);
    c2f c2a = cis(-PI_F * 4.0f * inv3sa);
    c2f c2b = cis(-PI_F * inv3sa);

    c2f Z[3][3];
    const float* sp = spec + (size_t)id * 9;
#pragma unroll
    for (int i = 0; i < 3; i++)
#pragma unroll
        for (int j = 0; j < 3; j++)
            Z[i][j] = { sp[i * 3 + j], 0.0f };
#pragma unroll
    for (int i = 0; i < 3; i++)
        frft3(Z[i][0], Z[i][1], Z[i][2], c1a, c1b, c2a, c2b, scl);
#pragma unroll
    for (int j = 0; j < 3; j++)
        frft3(Z[0][j], Z[1][j], Z[2][j], c1a, c1b, c2a, c2b, scl);

    float pw0 = polarw[0];
    float pw1 = polarw[1];

    int co = id >> 6, ci = id & 63;
    int nt = co >> 3, gid = co & 7;
    int ch = ci >> 4, r = ci & 15;
    int tig  = (r < 8) ? (r >> 1) : ((r - 8) >> 1);
    int word = (r < 8) ? 0 : 1;
    bool writer = ((ci & 1) == 0);

#pragma unroll
    for (int i = 0; i < 3; i++)
#pragma unroll
        for (int j = 0; j < 3; j++) {
            float re = Z[i][j].re, im = Z[i][j].im;
            float mag = sqrtf(re * re + im * im);
            float ang = atan2f(im, re);
            float k = pw0 * mag + pw1 * (ang * (1.0f / PI_F));
            float kn = __shfl_down_sync(0xffffffffu, k, 1);
            if (writer) {
                int tap = i * 3 + j;
                int s = ch * 9 + tap;
                __half2 h = __floats2half2_rn(k, kn);
                g_BfragW[(((s * 8 + nt) * 32) + gid * 4 + tig) * 2 + word] =
                    *reinterpret_cast<u32*>(&h);
            }
        }
}

// --------------------------------- conv mma ---------------------------------
__device__ __forceinline__ void mma16(float* c,
                                      u32 a0, u32 a1, u32 a2, u32 a3,
                                      u32 b0, u32 b1) {
    asm volatile(
        "mma.sync.aligned.m16n8k16.row.col.f32.f16.f16.f32 "
        "{%0,%1,%2,%3}, {%4,%5,%6,%7}, {%8,%9}, {%0,%1,%2,%3};"
        : "+f"(c[0]), "+f"(c[1]), "+f"(c[2]), "+f"(c[3])
        : "r"(a0), "r"(a1), "r"(a2), "r"(a3), "r"(b0), "r"(b1));
}

// tile decode: tile = n*196 + hy*7 + wx
__device__ __forceinline__ void tile_coords(int tile, int& h0, int& w0, int& n) {
    int wx = tile % 7;
    int r1 = tile / 7;
    int hy = r1 % 28;
    n = r1 / 28;
    w0 = wx * 32;
    h0 = hy * 8;
}

__global__ __launch_bounds__(128, 2)
void frfd_conv_mma(const float* __restrict__ x, float* __restrict__ out) {
    // dyn smem: [B fragments 18432 u32][A ring: 2 x 2880 u32]
    extern __shared__ __align__(16) u32 sm[];
    u32* const sB  = sm;
    u32* const sA0 = sm + B_WORDS;
    u32* const sA1 = sm + B_WORDS + A_WORDS;

    const int tid  = threadIdx.x;       // 128
    const int wz   = tid >> 5;          // warp 0..3 -> h row pair
    const int lane = tid & 31;
    const int gid  = lane >> 2;
    const int tig  = lane & 3;

    // per-thread A word offsets for the 9 tap-steps (conflict-free LDS)
    u32 dApack[9];
#pragma unroll
    for (int kt = 0; kt < 9; ++kt) {
        int tapoff = (kt / 3) * 36 + (kt % 3);
        int lo = tig * 360 + tapoff;
        int hi = lo + 4 * 360;
        dApack[kt] = (u32)lo | ((u32)hi << 16);
    }

    int mBase[2][2];
#pragma unroll
    for (int rh = 0; rh < 2; ++rh)
#pragma unroll
        for (int wt = 0; wt < 2; ++wt)
            mBase[rh][wt] = (2 * wz + rh) * 36 + wt * 16 + gid;

    // ---- one-time: stage B table (73.7KB) into smem ----
    {
        const uint4* src = reinterpret_cast<const uint4*>(g_BfragW);
        uint4* dst = reinterpret_cast<uint4*>(sB);
        for (int i = tid; i < B_WORDS / 4; i += 128) dst[i] = __ldg(src + i);
    }

    // ---- one-time prologue: stage (tile0, chunk0) into buffer 0 ----
    {
        int h0, w0, n;
        tile_coords(blockIdx.x, h0, w0, n);
        const float* xb = x + (size_t)n * 64 * 50176;
        for (int idx = tid; idx < 2720; idx += 128) {
            int ci2 = idx / 340;
            int rem = idx - ci2 * 340;
            int r   = rem / 34;
            int c   = rem - r * 34;
            int gh = h0 - 1 + r;
            int gw = w0 - 1 + c;
            float v0 = 0.0f, v1 = 0.0f;
            if ((unsigned)gh < 224u && (unsigned)gw < 224u) {
                const float* p = xb + (size_t)(2 * ci2) * 50176 + gh * 224 + gw;
                v0 = __ldg(p);
                v1 = __ldg(p + 50176);
            }
            __half2 h = __floats2half2_rn(v0, v1);
            sA0[ci2 * 360 + r * 36 + c] = *reinterpret_cast<u32*>(&h);
        }
    }
    __syncthreads();

    int p = 0;   // buffer parity (4 flips per tile -> consistent across tiles)

    for (int tile = blockIdx.x; tile < NTILES; tile += NBLOCKS) {
        int h0, w0, n;
        tile_coords(tile, h0, w0, n);

        float acc[2][2][8][4];
#pragma unroll
        for (int rh = 0; rh < 2; ++rh)
#pragma unroll
            for (int wt = 0; wt < 2; ++wt)
#pragma unroll
                for (int nt = 0; nt < 8; ++nt)
#pragma unroll
                    for (int c = 0; c < 4; ++c) acc[rh][wt][nt][c] = 0.0f;

        for (int ch = 0; ch < 4; ++ch) {
            const u32* __restrict__ aBuf = p ? sA1 : sA0;

            // ---- prefetch target: (tile, ch+1) or (tile+NBLOCKS, chunk 0) ----
            bool hasPre;
            int ph0, pw0l;
            const float* pxc;
            if (ch < 3) {
                hasPre = true;
                ph0 = h0; pw0l = w0;
                pxc = x + (size_t)n * 64 * 50176 + (size_t)(ch + 1) * 16 * 50176;
            } else {
                int ntile = tile + NBLOCKS;
                hasPre = (ntile < NTILES);
                int nn = 0;
                if (hasPre) tile_coords(ntile, ph0, pw0l, nn);
                else { ph0 = 0; pw0l = 0; }
                pxc = x + (size_t)nn * 64 * 50176;
            }

            u32 vpre[22];
            if (hasPre) {
#pragma unroll
                for (int k = 0; k < 22; ++k) {
                    int idx = tid + k * 128;
                    float v0 = 0.0f, v1 = 0.0f;
                    if (idx < 2720) {
                        int ci2 = idx / 340;
                        int rem = idx - ci2 * 340;
                        int r   = rem / 34;
                        int c   = rem - r * 34;
                        int gh = ph0 - 1 + r;
                        int gw = pw0l - 1 + c;
                        if ((unsigned)gh < 224u && (unsigned)gw < 224u) {
                            const float* pp = pxc + (size_t)(2 * ci2) * 50176 + gh * 224 + gw;
                            v0 = __ldg(pp);
                            v1 = __ldg(pp + 50176);
                        }
                    }
                    __half2 h = __floats2half2_rn(v0, v1);
                    vpre[k] = *reinterpret_cast<u32*>(&h);
                }
            }

            // ---- 9 tap-steps x (4 m-tiles x 8 n-tiles) k16 mma, B from smem ----
            const uint2* bChunk =
                reinterpret_cast<const uint2*>(sB) + (size_t)ch * 9 * 8 * 32 + lane;
#pragma unroll 3
            for (int kt = 0; kt < 9; ++kt) {
                u32 pk = dApack[kt];
                const u32* aLo = aBuf + (pk & 0xFFFFu);
                const u32* aHi = aBuf + (pk >> 16);
                u32 a[2][2][4];
#pragma unroll
                for (int rh = 0; rh < 2; ++rh)
#pragma unroll
                    for (int wt = 0; wt < 2; ++wt) {
                        int b = mBase[rh][wt];
                        a[rh][wt][0] = aLo[b];
                        a[rh][wt][1] = aLo[b + 8];
                        a[rh][wt][2] = aHi[b];
                        a[rh][wt][3] = aHi[b + 8];
                    }
                const uint2* bp = bChunk + (size_t)kt * 256;
#pragma unroll
                for (int nt = 0; nt < 8; ++nt) {
                    uint2 bb = bp[nt * 32];            // LDS.64, conflict-free
#pragma unroll
                    for (int rh = 0; rh < 2; ++rh)
#pragma unroll
                        for (int wt = 0; wt < 2; ++wt)
                            mma16(acc[rh][wt][nt],
                                  a[rh][wt][0], a[rh][wt][1],
                                  a[rh][wt][2], a[rh][wt][3],
                                  bb.x, bb.y);
                }
            }

            // ---- store prefetched chunk into the other buffer ----
            if (hasPre) {
                u32* dst = p ? sA0 : sA1;
#pragma unroll
                for (int k = 0; k < 22; ++k) {
                    int idx = tid + k * 128;
                    if (idx < 2720) {
                        int ci2 = idx / 340;
                        int rem = idx - ci2 * 340;
                        int r   = rem / 34;
                        int c   = rem - r * 34;
                        dst[ci2 * 360 + r * 36 + c] = vpre[k];
                    }
                }
            }
            __syncthreads();
            p ^= 1;
        }

        // ---- epilogue: scatter stores for this tile ----
        float* ob = out + (size_t)n * 64 * 50176;
#pragma unroll
        for (int nt = 0; nt < 8; ++nt) {
            int co = nt * 8 + tig * 2;
#pragma unroll
            for (int rh = 0; rh < 2; ++rh) {
                int h = h0 + 2 * wz + rh;
                float* p0 = ob + (size_t)co * 50176 + (size_t)h * 224 + w0 + gid;
                float* p1 = p0 + 50176;
#pragma unroll
                for (int wt = 0; wt < 2; ++wt) {
                    float* q0 = p0 + wt * 16;
                    float* q1 = p1 + wt * 16;
                    q0[0] = acc[rh][wt][nt][0];
                    q1[0] = acc[rh][wt][nt][1];
                    q0[8] = acc[rh][wt][nt][2];
                    q1[8] = acc[rh][wt][nt][3];
                }
            }
        }
    }
}

// --------------------------------- launcher ---------------------------------
extern "C" void kernel_launch(void* const* d_in, const int* in_sizes, int n_in,
                              void* d_out, int out_size) {
    int ix = 0, ispec = 1, ialpha = 2, ipw = 3;
    for (int i = 0; i < n_in; ++i) {
        int s = in_sizes[i];
        if (s == 16 * 64 * 224 * 224) ix = i;
        else if (s == 64 * 64 * 3 * 3) ispec = i;
        else if (s == 1) ialpha = i;
        else if (s == 2) ipw = i;
    }
    const float* x     = (const float*)d_in[ix];
    const float* spec  = (const float*)d_in[ispec];
    const float* alpha = (const float*)d_in[ialpha];
    const float* pw    = (const float*)d_in[ipw];
    float* out = (float*)d_out;

    frfd_wgen_kernel<<<32, 128>>>(spec, alpha, pw);

    const int shmem = (B_WORDS + 2 * A_WORDS) * 4;   // 96768 B
    cudaFuncSetAttribute(frfd_conv_mma,
                         cudaFuncAttributeMaxDynamicSharedMemorySize, shmem);
    frfd_conv_mma<<<NBLOCKS, 128, shmem>>>(x, out);
}